// round 16
// baseline (speedup 1.0000x reference)
#include <cuda_runtime.h>
#include <math.h>

#define NG 1024
#define IMG_H 128
#define IMG_W 128
#define FXc 128.0f
#define FYc 128.0f
#define CLIPX 0.65f   // 1.3 * TANX
#define CLIPY 0.65f   // 1.3 * TANY
#define NT 1024       // block threads (32 warps/SM)
#define NPIX 128      // 16x8 region
#define NSEG 8        // depth segments per pixel (NPIX*NSEG == NT)
#define NBLK 128      // one block per 16x8 region
#define KMAX 0xFFFFFFFFFFFFFFFFull

// dynamic shared (bytes): sgeo 16K | saux 16K | scol 16K | cgeo2 16K | caux2 16K |
//                         ccol2 16K | spth 4K | skey 8K  = 108KB
#define SMEM_DYN (NG*(16+16+16+16+16+16+4+8))

// ---------------- u64 warp bitonic stage ----------------
__device__ __forceinline__ void wstage64(unsigned long long& kk, int t, int stride, bool asc)
{
    unsigned long long ko = __shfl_xor_sync(0xffffffffu, kk, stride);
    bool lower = ((t & stride) == 0);
    bool take = asc ? (lower ? (kk > ko) : (kk < ko))
                    : (lower ? (kk < ko) : (kk > ko));
    if (take) kk = ko;
}

// ---------------- single-phase barrier-free kernel ----------------
__global__ __launch_bounds__(NT, 1)
void gauss_kernel(const float* __restrict__ means3D,
                  const float* __restrict__ opacities,
                  const float* __restrict__ shs,
                  const float* __restrict__ scales,
                  const float* __restrict__ rotations,
                  const float* __restrict__ vm,
                  const float* __restrict__ pm,
                  const float* __restrict__ campos,
                  const float* __restrict__ bg,
                  float* __restrict__ out)
{
    extern __shared__ char dsm[];
    float4* sgeo  = reinterpret_cast<float4*>(dsm);        // x,y,conA,conB
    float4* saux  = sgeo  + NG;                            // rx,ry,depth,conC
    float4* scol  = saux  + NG;                            // r,g,b,op
    float4* cgeo2 = scol  + NG;                            // sorted: x,y,conA,conB
    float4* caux2 = cgeo2 + NG;                            // sorted: conC,pth,op,-
    float4* ccol2 = caux2 + NG;                            // sorted: r,g,b,-
    float*  spth  = reinterpret_cast<float*>(ccol2 + NG);  // pth
    unsigned long long* skey = reinterpret_cast<unsigned long long*>(spth + NG);

    __shared__ float4 mseg[NSEG][NPIX];
    __shared__ int    scnt;

    int tid = threadIdx.x;
    int blk = blockIdx.x;
    int lane = tid & 31;

    if (tid == 0) scnt = 0;

    // ===== phase A: per-block prep of ALL gaussians incl. SH color (1/thread) =======
    {
        int i = tid;

        // issue all loads up front (conic + SH together: 32 warps hide latency)
        float mx = __ldg(&means3D[3*i+0]);
        float my = __ldg(&means3D[3*i+1]);
        float mz = __ldg(&means3D[3*i+2]);
        float4 q  = __ldg(reinterpret_cast<const float4*>(rotations) + i);
        float s0 = __ldg(&scales[3*i+0]);
        float s1 = __ldg(&scales[3*i+1]);
        float s2 = __ldg(&scales[3*i+2]);
        float op = __ldg(&opacities[i]);
        const float4* sh4 = reinterpret_cast<const float4*>(shs + i*48);
        float4 v0  = __ldg(sh4+0),  v1  = __ldg(sh4+1),  v2  = __ldg(sh4+2);
        float4 v3  = __ldg(sh4+3),  v4  = __ldg(sh4+4),  v5  = __ldg(sh4+5);
        float4 v6  = __ldg(sh4+6),  v7  = __ldg(sh4+7),  v8  = __ldg(sh4+8);
        float4 v9  = __ldg(sh4+9),  v10 = __ldg(sh4+10), v11 = __ldg(sh4+11);

        float pv0 = mx*vm[0] + my*vm[4] + mz*vm[8]  + vm[12];
        float pv1 = mx*vm[1] + my*vm[5] + mz*vm[9]  + vm[13];
        float pv2 = mx*vm[2] + my*vm[6] + mz*vm[10] + vm[14];
        float depth = pv2;

        float ph0 = mx*pm[0] + my*pm[4] + mz*pm[8]  + pm[12];
        float ph1 = mx*pm[1] + my*pm[5] + mz*pm[9]  + pm[13];
        float ph3 = mx*pm[3] + my*pm[7] + mz*pm[11] + pm[15];
        float invw = 1.0f / (ph3 + 1e-7f);
        float ppx = ph0 * invw, ppy = ph1 * invw;

        float qr = q.x, qx = q.y, qy = q.z, qz = q.w;
        float qn = rsqrtf(qr*qr + qx*qx + qy*qy + qz*qz);
        qr *= qn; qx *= qn; qy *= qn; qz *= qn;
        float R00 = 1.f - 2.f*(qy*qy + qz*qz), R01 = 2.f*(qx*qy - qr*qz), R02 = 2.f*(qx*qz + qr*qy);
        float R10 = 2.f*(qx*qy + qr*qz), R11 = 1.f - 2.f*(qx*qx + qz*qz), R12 = 2.f*(qy*qz - qr*qx);
        float R20 = 2.f*(qx*qz - qr*qy), R21 = 2.f*(qy*qz + qr*qx), R22 = 1.f - 2.f*(qx*qx + qy*qy);

        float M00 = R00*s0, M01 = R01*s1, M02 = R02*s2;
        float M10 = R10*s0, M11 = R11*s1, M12 = R12*s2;
        float M20 = R20*s0, M21 = R21*s1, M22 = R22*s2;

        float S00 = M00*M00 + M01*M01 + M02*M02;
        float S01 = M00*M10 + M01*M11 + M02*M12;
        float S02 = M00*M20 + M01*M21 + M02*M22;
        float S11 = M10*M10 + M11*M11 + M12*M12;
        float S12 = M10*M20 + M11*M21 + M12*M22;
        float S22 = M20*M20 + M21*M21 + M22*M22;

        float tz = (depth > 0.2f) ? depth : 1.0f;
        float invz = 1.0f / tz;
        float txtz = fminf(fmaxf(pv0*invz, -CLIPX), CLIPX) * tz;
        float tytz = fminf(fmaxf(pv1*invz, -CLIPY), CLIPY) * tz;
        float J00 = FXc*invz, J02 = -FXc*txtz*invz*invz;
        float J11 = FYc*invz, J12 = -FYc*tytz*invz*invz;

        float t00 = J00*vm[0]  + J02*vm[2];
        float t01 = J00*vm[4]  + J02*vm[6];
        float t02 = J00*vm[8]  + J02*vm[10];
        float t10 = J11*vm[1]  + J12*vm[2];
        float t11 = J11*vm[5]  + J12*vm[6];
        float t12 = J11*vm[9]  + J12*vm[10];

        float a = t00*t00*S00 + t01*t01*S11 + t02*t02*S22
                + 2.f*(t00*t01*S01 + t00*t02*S02 + t01*t02*S12) + 0.3f;
        float c = t10*t10*S00 + t11*t11*S11 + t12*t12*S22
                + 2.f*(t10*t11*S01 + t10*t12*S02 + t11*t12*S12) + 0.3f;
        float b = t00*t10*S00 + t01*t11*S11 + t02*t12*S22
                + (t00*t11 + t01*t10)*S01 + (t00*t12 + t02*t10)*S02 + (t01*t12 + t02*t11)*S12;

        float det = a*c - b*b;
        bool valid = (depth > 0.2f) && (det > 0.0f);
        float inv_det = 1.0f / ((det > 0.0f) ? det : 1.0f);
        float conA = c*inv_det, conB = -b*inv_det, conC = a*inv_det;

        float mid = 0.5f*(a + c);
        float lam1 = mid + sqrtf(fmaxf(0.1f, mid*mid - det));
        float radii = valid ? ceilf(3.0f * sqrtf(lam1)) : 0.0f;

        float xyx = ((ppx + 1.0f)*(float)IMG_W - 1.0f)*0.5f;
        float xyy = ((ppy + 1.0f)*(float)IMG_H - 1.0f)*0.5f;

        // SH color
        float dx = mx - campos[0], dy = my - campos[1], dz = mz - campos[2];
        float dn = rsqrtf(dx*dx + dy*dy + dz*dz);
        float x = dx*dn, y = dy*dn, z = dz*dn;
        float xx = x*x, yy = y*y, zz = z*z;
        float xy = x*y, yz = y*z, xz = x*z;

        float b0  = 0.28209479177387814f;
        float b1  = -0.4886025119029199f*y;
        float b2b = 0.4886025119029199f*z;
        float b3  = -0.4886025119029199f*x;
        float b4  = 1.0925484305920792f * xy;
        float b5  = -1.0925484305920792f * yz;
        float b6  = 0.31539156525252005f * (2.f*zz - xx - yy);
        float b7  = -1.0925484305920792f * xz;
        float b8  = 0.5462742152960396f * (xx - yy);
        float b9  = -0.5900435899266435f * y * (3.f*xx - yy);
        float b10 = 2.890611442640554f  * xy * z;
        float b11 = -0.4570457994644658f * y * (4.f*zz - xx - yy);
        float b12 = 0.3731763325901154f * z * (2.f*zz - 3.f*xx - 3.f*yy);
        float b13 = -0.4570457994644658f * x * (4.f*zz - xx - yy);
        float b14 = 1.445305721320277f  * z * (xx - yy);
        float b15 = -0.5900435899266435f * x * (xx - 3.f*yy);

        float r2, g2, bb2;
        r2   = b0*v0.x  + b1*v0.w  + b2b*v1.z  + b3*v2.y;
        g2   = b0*v0.y  + b1*v1.x  + b2b*v1.w  + b3*v2.z;
        bb2  = b0*v0.z  + b1*v1.y  + b2b*v2.x  + b3*v2.w;
        r2  += b4*v3.x  + b5*v3.w  + b6*v4.z   + b7*v5.y;
        g2  += b4*v3.y  + b5*v4.x  + b6*v4.w   + b7*v5.z;
        bb2 += b4*v3.z  + b5*v4.y  + b6*v5.x   + b7*v5.w;
        r2  += b8*v6.x  + b9*v6.w  + b10*v7.z  + b11*v8.y;
        g2  += b8*v6.y  + b9*v7.x  + b10*v7.w  + b11*v8.z;
        bb2 += b8*v6.z  + b9*v7.y  + b10*v8.x  + b11*v8.w;
        r2  += b12*v9.x + b13*v9.w + b14*v10.z + b15*v11.y;
        g2  += b12*v9.y + b13*v10.x+ b14*v10.w + b15*v11.z;
        bb2 += b12*v9.z + b13*v10.y+ b14*v11.x + b15*v11.w;

        r2  = fmaxf(r2 + 0.5f, 0.f);
        g2  = fmaxf(g2 + 0.5f, 0.f);
        bb2 = fmaxf(bb2 + 0.5f, 0.f);

        float mpth = logf(255.0f * op);
        float rxe, rye;
        if (valid && mpth > 0.0f) {
            rxe = sqrtf(2.0f*mpth*a);
            rye = sqrtf(2.0f*mpth*c);
        } else {
            rxe = -1.0f; rye = -1.0f;
        }

        sgeo[i] = make_float4(xyx, xyy, conA, conB);
        saux[i] = make_float4(rxe, rye, valid ? depth : INFINITY, conC);
        scol[i] = make_float4(r2, g2, bb2, op);
        spth[i] = -mpth;

        // radii output: this block owns gaussians [blk*8, blk*8+8)
        if ((i >> 3) == blk)
            out[IMG_H*IMG_W*3 + i] = radii;
    }
    __syncthreads();

    // ================= phase B: cull region survivors (1/thread) =====================
    int pix  = tid & (NPIX-1);          // 0..127
    int seg  = tid >> 7;                // 0..7
    int tx = pix & 15, ty = pix >> 4;   // 16 wide, 8 tall
    int rx0 = (blk & 7) * 16;
    int ry0 = (blk >> 3) * 8;
    float fx = (float)(rx0 + tx);
    float fy = (float)(ry0 + ty);
    float tminx = (float)rx0, tmaxx = tminx + 15.0f;
    float tminy = (float)ry0, tmaxy = tminy + 7.0f;
    float bgr = bg[0], bgg = bg[1], bgb = bg[2];

    {
        int i = tid;
        float4 ge = sgeo[i];
        float4 au = saux[i];
        float cx = fminf(fmaxf(ge.x, tminx), tmaxx);
        float cy = fminf(fmaxf(ge.y, tminy), tmaxy);
        bool keep = (fabsf(ge.x - cx) <= au.x) && (fabsf(ge.y - cy) <= au.y);
        unsigned m = __ballot_sync(0xffffffffu, keep);
        int base = 0;
        if (lane == 0 && m) base = atomicAdd(&scnt, __popc(m));
        base = __shfl_sync(0xffffffffu, base, 0);
        if (keep) {
            int pos = base + __popc(m & ((1u << lane) - 1u));
            skey[pos] = ((unsigned long long)__float_as_uint(au.z) << 32) | (unsigned)i;
        }
    }
    __syncthreads();
    int cnt = scnt;

    float Trun = 1.0f;
    float cr = 0.f, cg = 0.f, cb = 0.f;

    if (cnt > 0) {
        // ================= phase C: sort survivors (1 elem/thread) ===================
        {
            int P = 32;
            while (P < cnt) P <<= 1;
            unsigned long long kk = (tid < cnt) ? skey[tid] : KMAX;
            #pragma unroll
            for (int size = 2; size <= 32; size <<= 1) {
                bool asc = ((tid & size) == 0);
                #pragma unroll
                for (int stride = size >> 1; stride >= 1; stride >>= 1)
                    wstage64(kk, tid, stride, asc);
            }
            skey[tid] = kk;
            __syncthreads();
            for (int size = 64; size <= P; size <<= 1) {
                bool asc = ((tid & size) == 0);
                for (int stride = size >> 1; stride >= 32; stride >>= 1) {
                    int j = tid ^ stride;
                    if (j > tid) {
                        unsigned long long a2 = skey[tid], b2 = skey[j];
                        if ((a2 > b2) == asc) { skey[tid] = b2; skey[j] = a2; }
                    }
                    __syncthreads();
                }
                kk = skey[tid];
                #pragma unroll
                for (int stride = 16; stride >= 1; stride >>= 1)
                    wstage64(kk, tid, stride, asc);
                skey[tid] = kk;
                __syncthreads();
            }
        }

        // ===== phase D: shared->shared gather into sorted SoA (no global loads) ======
        if (tid < cnt) {
            int idx = (int)(skey[tid] & 0xFFFFFu);
            float4 co = scol[idx];
            cgeo2[tid] = sgeo[idx];
            caux2[tid] = make_float4(saux[idx].w, spth[idx], co.w, 0.0f); // conC,pth,op
            ccol2[tid] = co;                                              // r,g,b,(op)
        }
        __syncthreads();

        // ================= phase E: single-pass segmented composite ==================
        float scr = 0.f, scg = 0.f, scb = 0.f, sT = 1.0f;
        {
            int js = (cnt * seg) / NSEG;
            int je = (cnt * (seg+1)) / NSEG;
            for (int j = js; j < je; j++) {
                float4 g4 = cgeo2[j];
                float4 au = caux2[j];
                float dx = g4.x - fx;
                float dy = g4.y - fy;
                float power = -0.5f*(g4.z*dx*dx + au.x*dy*dy) - g4.w*dx*dy;
                if (power > 0.0f || power < au.y) continue;
                float alpha = fminf(0.99f, au.z * __expf(power));
                if (alpha < (1.0f/255.0f)) continue;
                float4 col = ccol2[j];
                float w = sT * alpha;
                scr += w * col.x;
                scg += w * col.y;
                scb += w * col.z;
                sT  *= (1.0f - alpha);
            }
        }
        mseg[seg][pix] = make_float4(scr, scg, scb, sT);
        __syncthreads();

        // segment-prefix exact merge on seg==0 threads
        if (seg == 0) {
            int s;
            #pragma unroll
            for (s = 0; s < NSEG; s++) {
                float4 ms = mseg[s][pix];
                if (Trun * ms.w >= 1e-4f) {
                    cr += Trun * ms.x;
                    cg += Trun * ms.y;
                    cb += Trun * ms.z;
                    Trun *= ms.w;
                } else break;
            }
            if (s < NSEG) {
                // 1e-4 crossing inside segment s: exact serial re-walk of it
                int js = (cnt * s) / NSEG;
                int je = (cnt * (s+1)) / NSEG;
                for (int j = js; j < je; j++) {
                    float4 g4 = cgeo2[j];
                    float4 au = caux2[j];
                    float dx = g4.x - fx;
                    float dy = g4.y - fy;
                    float power = -0.5f*(g4.z*dx*dx + au.x*dy*dy) - g4.w*dx*dy;
                    if (power > 0.0f || power < au.y) continue;
                    float alpha = fminf(0.99f, au.z * __expf(power));
                    if (alpha < (1.0f/255.0f)) continue;
                    float Tnew = Trun * (1.0f - alpha);
                    if (Tnew < 1e-4f) break;
                    float4 col = ccol2[j];
                    float w = Trun * alpha;
                    cr += w * col.x;
                    cg += w * col.y;
                    cb += w * col.z;
                    Trun = Tnew;
                }
            }
        }
    }

    if (seg == 0) {
        int pxi = (ry0 + ty)*IMG_W + (rx0 + tx);
        out[0*IMG_H*IMG_W + pxi] = cr + bgr*Trun;
        out[1*IMG_H*IMG_W + pxi] = cg + bgg*Trun;
        out[2*IMG_H*IMG_W + pxi] = cb + bgb*Trun;
    }
}

// ---------------- launch ----------------
extern "C" void kernel_launch(void* const* d_in, const int* in_sizes, int n_in,
                              void* d_out, int out_size)
{
    const float* means3D   = (const float*)d_in[0];
    // d_in[1] = means2D (unused)
    const float* opacities = (const float*)d_in[2];
    const float* shs       = (const float*)d_in[3];
    const float* scales    = (const float*)d_in[4];
    const float* rotations = (const float*)d_in[5];
    const float* viewm     = (const float*)d_in[6];
    const float* projm     = (const float*)d_in[7];
    const float* campos    = (const float*)d_in[8];
    const float* bg        = (const float*)d_in[9];
    float* out = (float*)d_out;

    cudaFuncSetAttribute(gauss_kernel,
                         cudaFuncAttributeMaxDynamicSharedMemorySize, SMEM_DYN);
    gauss_kernel<<<NBLK, NT, SMEM_DYN>>>(means3D, opacities, shs, scales, rotations,
                                         viewm, projm, campos, bg, out);
}

// round 17
// speedup vs baseline: 1.1385x; 1.1385x over previous
#include <cuda_runtime.h>
#include <math.h>

#define NG 1024
#define IMG_H 128
#define IMG_W 128
#define FXc 128.0f
#define FYc 128.0f
#define CLIPX 0.65f   // 1.3 * TANX
#define CLIPY 0.65f   // 1.3 * TANY
#define NT 1024       // block threads (32 warps/SM)
#define NPIX 128      // 16x8 region
#define NSEG 8        // depth segments per pixel (NPIX*NSEG == NT)
#define NBLK 128      // one block per 16x8 region
#define KMAX 0xFFFFFFFFFFFFFFFFull

// dynamic shared (bytes): sgeo 16K | saux 16K | scol 16K | cgeo2 16K | caux2 16K |
//                         ccol2 16K | spth 4K | skey 8K  = 108KB
#define SMEM_DYN (NG*(16+16+16+16+16+16+4+8))

// ---------------- u64 warp bitonic stage ----------------
__device__ __forceinline__ void wstage64(unsigned long long& kk, int t, int stride, bool asc)
{
    unsigned long long ko = __shfl_xor_sync(0xffffffffu, kk, stride);
    bool lower = ((t & stride) == 0);
    bool take = asc ? (lower ? (kk > ko) : (kk < ko))
                    : (lower ? (kk < ko) : (kk > ko));
    if (take) kk = ko;
}

// ---------------- single-phase barrier-free kernel ----------------
__global__ __launch_bounds__(NT, 1)
void gauss_kernel(const float* __restrict__ means3D,
                  const float* __restrict__ opacities,
                  const float* __restrict__ shs,
                  const float* __restrict__ scales,
                  const float* __restrict__ rotations,
                  const float* __restrict__ vm,
                  const float* __restrict__ pm,
                  const float* __restrict__ campos,
                  const float* __restrict__ bg,
                  float* __restrict__ out)
{
    extern __shared__ char dsm[];
    float4* sgeo  = reinterpret_cast<float4*>(dsm);        // x,y,conA,conB
    float4* saux  = sgeo  + NG;                            // rx,ry,depth,conC
    float4* scol  = saux  + NG;                            // r,g,b,op
    float4* cgeo2 = scol  + NG;                            // sorted: x,y,conA,conB
    float4* caux2 = cgeo2 + NG;                            // sorted: conC,pth,op,-
    float4* ccol2 = caux2 + NG;                            // sorted: r,g,b,-
    float*  spth  = reinterpret_cast<float*>(ccol2 + NG);  // pth
    unsigned long long* skey = reinterpret_cast<unsigned long long*>(spth + NG);

    __shared__ float4 mseg[NSEG][NPIX];
    __shared__ int    scnt;

    int tid = threadIdx.x;
    int blk = blockIdx.x;
    int lane = tid & 31;

    if (tid == 0) scnt = 0;

    // ===== phase A1: conic prep of ALL gaussians (1/thread) — SEPARATE reg scope ====
    {
        int i = tid;

        float mx = __ldg(&means3D[3*i+0]);
        float my = __ldg(&means3D[3*i+1]);
        float mz = __ldg(&means3D[3*i+2]);
        float4 q  = __ldg(reinterpret_cast<const float4*>(rotations) + i);
        float s0 = __ldg(&scales[3*i+0]);
        float s1 = __ldg(&scales[3*i+1]);
        float s2 = __ldg(&scales[3*i+2]);
        float op = __ldg(&opacities[i]);

        float pv0 = mx*vm[0] + my*vm[4] + mz*vm[8]  + vm[12];
        float pv1 = mx*vm[1] + my*vm[5] + mz*vm[9]  + vm[13];
        float pv2 = mx*vm[2] + my*vm[6] + mz*vm[10] + vm[14];
        float depth = pv2;

        float ph0 = mx*pm[0] + my*pm[4] + mz*pm[8]  + pm[12];
        float ph1 = mx*pm[1] + my*pm[5] + mz*pm[9]  + pm[13];
        float ph3 = mx*pm[3] + my*pm[7] + mz*pm[11] + pm[15];
        float invw = 1.0f / (ph3 + 1e-7f);
        float ppx = ph0 * invw, ppy = ph1 * invw;

        float qr = q.x, qx = q.y, qy = q.z, qz = q.w;
        float qn = rsqrtf(qr*qr + qx*qx + qy*qy + qz*qz);
        qr *= qn; qx *= qn; qy *= qn; qz *= qn;
        float R00 = 1.f - 2.f*(qy*qy + qz*qz), R01 = 2.f*(qx*qy - qr*qz), R02 = 2.f*(qx*qz + qr*qy);
        float R10 = 2.f*(qx*qy + qr*qz), R11 = 1.f - 2.f*(qx*qx + qz*qz), R12 = 2.f*(qy*qz - qr*qx);
        float R20 = 2.f*(qx*qz - qr*qy), R21 = 2.f*(qy*qz + qr*qx), R22 = 1.f - 2.f*(qx*qx + qy*qy);

        float M00 = R00*s0, M01 = R01*s1, M02 = R02*s2;
        float M10 = R10*s0, M11 = R11*s1, M12 = R12*s2;
        float M20 = R20*s0, M21 = R21*s1, M22 = R22*s2;

        float S00 = M00*M00 + M01*M01 + M02*M02;
        float S01 = M00*M10 + M01*M11 + M02*M12;
        float S02 = M00*M20 + M01*M21 + M02*M22;
        float S11 = M10*M10 + M11*M11 + M12*M12;
        float S12 = M10*M20 + M11*M21 + M12*M22;
        float S22 = M20*M20 + M21*M21 + M22*M22;

        float tz = (depth > 0.2f) ? depth : 1.0f;
        float invz = 1.0f / tz;
        float txtz = fminf(fmaxf(pv0*invz, -CLIPX), CLIPX) * tz;
        float tytz = fminf(fmaxf(pv1*invz, -CLIPY), CLIPY) * tz;
        float J00 = FXc*invz, J02 = -FXc*txtz*invz*invz;
        float J11 = FYc*invz, J12 = -FYc*tytz*invz*invz;

        float t00 = J00*vm[0]  + J02*vm[2];
        float t01 = J00*vm[4]  + J02*vm[6];
        float t02 = J00*vm[8]  + J02*vm[10];
        float t10 = J11*vm[1]  + J12*vm[2];
        float t11 = J11*vm[5]  + J12*vm[6];
        float t12 = J11*vm[9]  + J12*vm[10];

        float a = t00*t00*S00 + t01*t01*S11 + t02*t02*S22
                + 2.f*(t00*t01*S01 + t00*t02*S02 + t01*t02*S12) + 0.3f;
        float c = t10*t10*S00 + t11*t11*S11 + t12*t12*S22
                + 2.f*(t10*t11*S01 + t10*t12*S02 + t11*t12*S12) + 0.3f;
        float b = t00*t10*S00 + t01*t11*S11 + t02*t12*S22
                + (t00*t11 + t01*t10)*S01 + (t00*t12 + t02*t10)*S02 + (t01*t12 + t02*t11)*S12;

        float det = a*c - b*b;
        bool valid = (depth > 0.2f) && (det > 0.0f);
        float inv_det = 1.0f / ((det > 0.0f) ? det : 1.0f);
        float conA = c*inv_det, conB = -b*inv_det, conC = a*inv_det;

        float mid = 0.5f*(a + c);
        float lam1 = mid + sqrtf(fmaxf(0.1f, mid*mid - det));
        float radii = valid ? ceilf(3.0f * sqrtf(lam1)) : 0.0f;

        float xyx = ((ppx + 1.0f)*(float)IMG_W - 1.0f)*0.5f;
        float xyy = ((ppy + 1.0f)*(float)IMG_H - 1.0f)*0.5f;

        float mpth = logf(255.0f * op);
        float rxe, rye;
        if (valid && mpth > 0.0f) {
            rxe = sqrtf(2.0f*mpth*a);
            rye = sqrtf(2.0f*mpth*c);
        } else {
            rxe = -1.0f; rye = -1.0f;
        }

        sgeo[i] = make_float4(xyx, xyy, conA, conB);
        saux[i] = make_float4(rxe, rye, valid ? depth : INFINITY, conC);
        spth[i] = -mpth;
        scol[i].w = op;   // op slot; rgb filled in phase A2

        // radii output: this block owns gaussians [blk*8, blk*8+8)
        if ((i >> 3) == blk)
            out[IMG_H*IMG_W*3 + i] = radii;
    }

    // ===== phase A2: SH color for ALL gaussians (fresh reg scope, means L1-hot) =====
    {
        int i = tid;
        float mx = __ldg(&means3D[3*i+0]);
        float my = __ldg(&means3D[3*i+1]);
        float mz = __ldg(&means3D[3*i+2]);
        const float4* sh4 = reinterpret_cast<const float4*>(shs + i*48);
        float4 v0  = __ldg(sh4+0),  v1  = __ldg(sh4+1),  v2  = __ldg(sh4+2);
        float4 v3  = __ldg(sh4+3),  v4  = __ldg(sh4+4),  v5  = __ldg(sh4+5);
        float4 v6  = __ldg(sh4+6),  v7  = __ldg(sh4+7),  v8  = __ldg(sh4+8);
        float4 v9  = __ldg(sh4+9),  v10 = __ldg(sh4+10), v11 = __ldg(sh4+11);

        float dx = mx - campos[0], dy = my - campos[1], dz = mz - campos[2];
        float dn = rsqrtf(dx*dx + dy*dy + dz*dz);
        float x = dx*dn, y = dy*dn, z = dz*dn;
        float xx = x*x, yy = y*y, zz = z*z;
        float xy = x*y, yz = y*z, xz = x*z;

        float b0  = 0.28209479177387814f;
        float b1  = -0.4886025119029199f*y;
        float b2b = 0.4886025119029199f*z;
        float b3  = -0.4886025119029199f*x;
        float b4  = 1.0925484305920792f * xy;
        float b5  = -1.0925484305920792f * yz;
        float b6  = 0.31539156525252005f * (2.f*zz - xx - yy);
        float b7  = -1.0925484305920792f * xz;
        float b8  = 0.5462742152960396f * (xx - yy);
        float b9  = -0.5900435899266435f * y * (3.f*xx - yy);
        float b10 = 2.890611442640554f  * xy * z;
        float b11 = -0.4570457994644658f * y * (4.f*zz - xx - yy);
        float b12 = 0.3731763325901154f * z * (2.f*zz - 3.f*xx - 3.f*yy);
        float b13 = -0.4570457994644658f * x * (4.f*zz - xx - yy);
        float b14 = 1.445305721320277f  * z * (xx - yy);
        float b15 = -0.5900435899266435f * x * (xx - 3.f*yy);

        float r2, g2, bb2;
        r2   = b0*v0.x  + b1*v0.w  + b2b*v1.z  + b3*v2.y;
        g2   = b0*v0.y  + b1*v1.x  + b2b*v1.w  + b3*v2.z;
        bb2  = b0*v0.z  + b1*v1.y  + b2b*v2.x  + b3*v2.w;
        r2  += b4*v3.x  + b5*v3.w  + b6*v4.z   + b7*v5.y;
        g2  += b4*v3.y  + b5*v4.x  + b6*v4.w   + b7*v5.z;
        bb2 += b4*v3.z  + b5*v4.y  + b6*v5.x   + b7*v5.w;
        r2  += b8*v6.x  + b9*v6.w  + b10*v7.z  + b11*v8.y;
        g2  += b8*v6.y  + b9*v7.x  + b10*v7.w  + b11*v8.z;
        bb2 += b8*v6.z  + b9*v7.y  + b10*v8.x  + b11*v8.w;
        r2  += b12*v9.x + b13*v9.w + b14*v10.z + b15*v11.y;
        g2  += b12*v9.y + b13*v10.x+ b14*v10.w + b15*v11.z;
        bb2 += b12*v9.z + b13*v10.y+ b14*v11.x + b15*v11.w;

        scol[i].x = fmaxf(r2 + 0.5f, 0.f);
        scol[i].y = fmaxf(g2 + 0.5f, 0.f);
        scol[i].z = fmaxf(bb2 + 0.5f, 0.f);
    }
    __syncthreads();

    // ================= phase B: cull region survivors (1/thread) =====================
    int pix  = tid & (NPIX-1);          // 0..127
    int seg  = tid >> 7;                // 0..7
    int tx = pix & 15, ty = pix >> 4;   // 16 wide, 8 tall
    int rx0 = (blk & 7) * 16;
    int ry0 = (blk >> 3) * 8;
    float fx = (float)(rx0 + tx);
    float fy = (float)(ry0 + ty);
    float tminx = (float)rx0, tmaxx = tminx + 15.0f;
    float tminy = (float)ry0, tmaxy = tminy + 7.0f;
    float bgr = bg[0], bgg = bg[1], bgb = bg[2];

    {
        int i = tid;
        float4 ge = sgeo[i];
        float4 au = saux[i];
        float cx = fminf(fmaxf(ge.x, tminx), tmaxx);
        float cy = fminf(fmaxf(ge.y, tminy), tmaxy);
        bool keep = (fabsf(ge.x - cx) <= au.x) && (fabsf(ge.y - cy) <= au.y);
        unsigned m = __ballot_sync(0xffffffffu, keep);
        int base = 0;
        if (lane == 0 && m) base = atomicAdd(&scnt, __popc(m));
        base = __shfl_sync(0xffffffffu, base, 0);
        if (keep) {
            int pos = base + __popc(m & ((1u << lane) - 1u));
            skey[pos] = ((unsigned long long)__float_as_uint(au.z) << 32) | (unsigned)i;
        }
    }
    __syncthreads();
    int cnt = scnt;

    float Trun = 1.0f;
    float cr = 0.f, cg = 0.f, cb = 0.f;

    if (cnt > 0) {
        // ================= phase C: sort survivors (1 elem/thread) ===================
        {
            int P = 32;
            while (P < cnt) P <<= 1;
            unsigned long long kk = (tid < cnt) ? skey[tid] : KMAX;
            #pragma unroll
            for (int size = 2; size <= 32; size <<= 1) {
                bool asc = ((tid & size) == 0);
                #pragma unroll
                for (int stride = size >> 1; stride >= 1; stride >>= 1)
                    wstage64(kk, tid, stride, asc);
            }
            skey[tid] = kk;
            __syncthreads();
            for (int size = 64; size <= P; size <<= 1) {
                bool asc = ((tid & size) == 0);
                for (int stride = size >> 1; stride >= 32; stride >>= 1) {
                    int j = tid ^ stride;
                    if (j > tid) {
                        unsigned long long a2 = skey[tid], b2 = skey[j];
                        if ((a2 > b2) == asc) { skey[tid] = b2; skey[j] = a2; }
                    }
                    __syncthreads();
                }
                kk = skey[tid];
                #pragma unroll
                for (int stride = 16; stride >= 1; stride >>= 1)
                    wstage64(kk, tid, stride, asc);
                skey[tid] = kk;
                __syncthreads();
            }
        }

        // ===== phase D: shared->shared gather into sorted SoA (no global loads) ======
        if (tid < cnt) {
            int idx = (int)(skey[tid] & 0xFFFFFu);
            float4 co = scol[idx];
            cgeo2[tid] = sgeo[idx];
            caux2[tid] = make_float4(saux[idx].w, spth[idx], co.w, 0.0f); // conC,pth,op
            ccol2[tid] = co;                                              // r,g,b,(op)
        }
        __syncthreads();

        // ================= phase E: single-pass segmented composite ==================
        float scr = 0.f, scg = 0.f, scb = 0.f, sT = 1.0f;
        {
            int js = (cnt * seg) / NSEG;
            int je = (cnt * (seg+1)) / NSEG;
            for (int j = js; j < je; j++) {
                float4 g4 = cgeo2[j];
                float4 au = caux2[j];
                float dx = g4.x - fx;
                float dy = g4.y - fy;
                float power = -0.5f*(g4.z*dx*dx + au.x*dy*dy) - g4.w*dx*dy;
                if (power > 0.0f || power < au.y) continue;
                float alpha = fminf(0.99f, au.z * __expf(power));
                if (alpha < (1.0f/255.0f)) continue;
                float4 col = ccol2[j];
                float w = sT * alpha;
                scr += w * col.x;
                scg += w * col.y;
                scb += w * col.z;
                sT  *= (1.0f - alpha);
            }
        }
        mseg[seg][pix] = make_float4(scr, scg, scb, sT);
        __syncthreads();

        // segment-prefix exact merge on seg==0 threads
        if (seg == 0) {
            int s;
            #pragma unroll
            for (s = 0; s < NSEG; s++) {
                float4 ms = mseg[s][pix];
                if (Trun * ms.w >= 1e-4f) {
                    cr += Trun * ms.x;
                    cg += Trun * ms.y;
                    cb += Trun * ms.z;
                    Trun *= ms.w;
                } else break;
            }
            if (s < NSEG) {
                // 1e-4 crossing inside segment s: exact serial re-walk of it
                int js = (cnt * s) / NSEG;
                int je = (cnt * (s+1)) / NSEG;
                for (int j = js; j < je; j++) {
                    float4 g4 = cgeo2[j];
                    float4 au = caux2[j];
                    float dx = g4.x - fx;
                    float dy = g4.y - fy;
                    float power = -0.5f*(g4.z*dx*dx + au.x*dy*dy) - g4.w*dx*dy;
                    if (power > 0.0f || power < au.y) continue;
                    float alpha = fminf(0.99f, au.z * __expf(power));
                    if (alpha < (1.0f/255.0f)) continue;
                    float Tnew = Trun * (1.0f - alpha);
                    if (Tnew < 1e-4f) break;
                    float4 col = ccol2[j];
                    float w = Trun * alpha;
                    cr += w * col.x;
                    cg += w * col.y;
                    cb += w * col.z;
                    Trun = Tnew;
                }
            }
        }
    }

    if (seg == 0) {
        int pxi = (ry0 + ty)*IMG_W + (rx0 + tx);
        out[0*IMG_H*IMG_W + pxi] = cr + bgr*Trun;
        out[1*IMG_H*IMG_W + pxi] = cg + bgg*Trun;
        out[2*IMG_H*IMG_W + pxi] = cb + bgb*Trun;
    }
}

// ---------------- launch ----------------
extern "C" void kernel_launch(void* const* d_in, const int* in_sizes, int n_in,
                              void* d_out, int out_size)
{
    const float* means3D   = (const float*)d_in[0];
    // d_in[1] = means2D (unused)
    const float* opacities = (const float*)d_in[2];
    const float* shs       = (const float*)d_in[3];
    const float* scales    = (const float*)d_in[4];
    const float* rotations = (const float*)d_in[5];
    const float* viewm     = (const float*)d_in[6];
    const float* projm     = (const float*)d_in[7];
    const float* campos    = (const float*)d_in[8];
    const float* bg        = (const float*)d_in[9];
    float* out = (float*)d_out;

    cudaFuncSetAttribute(gauss_kernel,
                         cudaFuncAttributeMaxDynamicSharedMemorySize, SMEM_DYN);
    gauss_kernel<<<NBLK, NT, SMEM_DYN>>>(means3D, opacities, shs, scales, rotations,
                                         viewm, projm, campos, bg, out);
}